// round 14
// baseline (speedup 1.0000x reference)
#include <cuda_runtime.h>
#include <cuda_fp16.h>
#include <cstdint>

#define C_IN   64
#define C_OUT  64
#define Hdim   224
#define Wdim   224
#define HW     (Hdim * Wdim)
#define NTHR   448

// B weight smem: u64 units, index = ((tap*4+ks)*8 + wn*4 + nt)*32 + gr*4 + tc
#define WS_BYTES (9 * 4 * 8 * 32 * 8)   // 73728
#define X_OFF    WS_BYTES
// fp16 x ring: 5 slots x [cipair 32 (stride 232 u32)]; halo j=3 (col -1), interior j=4..227, halo j=228
#define PXS    232
#define SLOTU  (32 * PXS)               // 7424 u32
#define NSLOT  5
#define SMEM_TOTAL (X_OFF + NSLOT * SLOTU * 4)   // 222208 B

// packed fp16 ci-pairs of x: [n][cipair 32][h][w]
__device__ __align__(16) uint32_t g_xh[16 * 32 * HW];
// ternary weights, LDS.64-friendly fragment layout (see ternarize)
__device__ __align__(16) unsigned short g_twB[9 * 4 * 8 * 32 * 4];
__device__ float g_alpha[C_OUT];

// ---------------------------------------------------------------- helpers
__device__ __forceinline__ uint32_t smem_u32(const void* p) {
    uint32_t a;
    asm("{ .reg .u64 t; cvta.to.shared.u64 t, %1; cvt.u32.u64 %0, t; }" : "=r"(a) : "l"(p));
    return a;
}
__device__ __forceinline__ void cp16(uint32_t dst, const void* src, int sz) {
    asm volatile("cp.async.cg.shared.global [%0], [%1], 16, %2;"
                 :: "r"(dst), "l"(src), "r"(sz) : "memory");
}
__device__ __forceinline__ uint32_t packh2(float lo, float hi) {
    return (uint32_t)__half_as_ushort(__float2half_rn(lo)) |
           ((uint32_t)__half_as_ushort(__float2half_rn(hi)) << 16);
}
__device__ __forceinline__ void mma_h(float* c, const uint32_t* a, uint32_t b0, uint32_t b1) {
    asm volatile(
        "mma.sync.aligned.m16n8k16.row.col.f32.f16.f16.f32 "
        "{%0,%1,%2,%3}, {%4,%5,%6,%7}, {%8,%9}, {%0,%1,%2,%3};"
        : "+f"(c[0]), "+f"(c[1]), "+f"(c[2]), "+f"(c[3])
        : "r"(a[0]), "r"(a[1]), "r"(a[2]), "r"(a[3]), "r"(b0), "r"(b1));
}

// ---------------------------------------------------------------- prepass: f32 -> packed fp16 pairs
__global__ void __launch_bounds__(256) prepass_kernel(const float* __restrict__ x) {
    int idx = blockIdx.x * 256 + threadIdx.x;
    int u = idx * 4;
    int n = u / (32 * HW);
    int r = u - n * (32 * HW);
    int c = r / HW;
    int p = r - c * HW;
    const float4 a = *(const float4*)(x + ((size_t)(n * 64 + 2 * c) * HW + p));
    const float4 b = *(const float4*)(x + ((size_t)(n * 64 + 2 * c + 1) * HW + p));
    uint4 o;
    o.x = packh2(a.x, b.x);
    o.y = packh2(a.y, b.y);
    o.z = packh2(a.z, b.z);
    o.w = packh2(a.w, b.w);
    *(uint4*)(g_xh + u) = o;
}

// ---------------------------------------------------------------- ternarize
__global__ void ternarize_kernel(const float* __restrict__ weight) {
    __shared__ float red[256], red2[256];
    __shared__ float s_delta, s_alpha;
    const int co = blockIdx.x, tid = threadIdx.x;
    const float* w = weight + co * 576;

    float v0 = (tid < 576) ? w[tid] : 0.0f;
    float v1 = (tid + 256 < 576) ? w[tid + 256] : 0.0f;
    float v2 = (tid + 512 < 576) ? w[tid + 512] : 0.0f;
    float a0 = fabsf(v0), a1 = fabsf(v1), a2 = fabsf(v2);

    red[tid] = a0 + a1 + a2;
    __syncthreads();
    for (int s = 128; s > 0; s >>= 1) { if (tid < s) red[tid] += red[tid + s]; __syncthreads(); }
    if (tid == 0) s_delta = (float)(0.7 / 576.0) * red[0];
    __syncthreads();
    const float delta = s_delta;

    float m0 = (a0 > delta) ? 1.f : 0.f, m1 = (a1 > delta) ? 1.f : 0.f, m2 = (a2 > delta) ? 1.f : 0.f;
    red[tid] = m0 * a0 + m1 * a1 + m2 * a2;
    red2[tid] = m0 + m1 + m2;
    __syncthreads();
    for (int s = 128; s > 0; s >>= 1) {
        if (tid < s) { red[tid] += red[tid + s]; red2[tid] += red2[tid + s]; }
        __syncthreads();
    }
    if (tid == 0) {
        float cnt = red2[0]; if (cnt < 0.5f) cnt = 1.0f;
        s_alpha = fmaxf(red[0] / cnt, 1e-4f);
        g_alpha[co] = s_alpha;
    }
    __syncthreads();

    const int wn = co >> 5, nt = (co >> 3) & 3, grb = co & 7;
#pragma unroll
    for (int q = 0; q < 3; q++) {
        int f = tid + q * 256;
        if (f < 576) {
            float v = (q == 0) ? v0 : (q == 1) ? v1 : v2;
            float t = (v > delta) ? 1.0f : ((v < -delta) ? -1.0f : 0.0f);
            int ci = f / 9, tap = f % 9;     // weight layout [co][ci][kh][kw]
            int ks = ci >> 4, r = ci & 15;
            int word = r >> 3, rr = r & 7;
            int tcb = rr >> 1, e = rr & 1;
            int u64idx = (((tap * 4 + ks) * 8 + wn * 4 + nt) * 32) + grb * 4 + tcb;
            g_twB[u64idx * 4 + word * 2 + e] = __half_as_ushort(__float2half_rn(t));
        }
    }
}

// ---------------------------------------------------------------- row staging (cp.async, one group per row)
// 32 cipairs x 56 chunks (224 cols / 4) = 1792 chunks = 4 per thread
__device__ __forceinline__ void cp_stage(uint32_t sxa, int n, int row, int tid) {
    const bool rok = (unsigned)row < (unsigned)Hdim;
    const int srow = rok ? row : 0;
    const int sz16 = rok ? 16 : 0;
    const uint32_t slot_b = sxa + (uint32_t)((row + NSLOT * 2) % NSLOT) * (SLOTU * 4);
    const uint32_t* xb = g_xh + (size_t)n * 32 * HW + (size_t)srow * Wdim;
#pragma unroll
    for (int k = 0; k < 4; k++) {
        int idx = tid + k * NTHR;            // 0..1791
        int c = idx / 56;                    // cipair 0..31
        int q = (idx - c * 56) * 4;          // col 0..220
        cp16(slot_b + (uint32_t)(c * PXS + 4 + q) * 4,
             xb + (size_t)c * HW + q, sz16);
    }
    asm volatile("cp.async.commit_group;" ::: "memory");
}

// A fragment load (one kstep, 2 m-tiles)
#define LOAD_A(A, ap)                                  \
    do {                                               \
        const uint32_t* _a0 = (ap);                    \
        (A)[0][0] = _a0[0];                            \
        (A)[0][1] = _a0[8];                            \
        (A)[0][2] = _a0[4 * PXS];                      \
        (A)[0][3] = _a0[4 * PXS + 8];                  \
        const uint32_t* _a1 = (ap) + 16;               \
        (A)[1][0] = _a1[0];                            \
        (A)[1][1] = _a1[8];                            \
        (A)[1][2] = _a1[4 * PXS];                      \
        (A)[1][3] = _a1[4 * PXS + 8];                  \
    } while (0)

// ---------------------------------------------------------------- conv (persistent, 2 rows/iter)
// grid (148). 448 thr = 14 warps: 7 M-warps (32 px, full 224 row) x 2 N-warps (32 co).
// Chunks: first 16 CTAs take 26 rows, remaining 132 take 24 (16*26 + 132*24 = 3584).
// All chunk starts even, image boundary (224) even -> every segment has even length.
__global__ void __launch_bounds__(NTHR, 1)
conv_kernel(const float* __restrict__ bias, float* __restrict__ out) {
    extern __shared__ char smem[];
    const uint2* B64 = (const uint2*)smem;
    uint32_t* sx = (uint32_t*)(smem + X_OFF);
    const uint32_t wsa = smem_u32(smem);
    const uint32_t sxa = smem_u32(smem + X_OFF);

    const int tid = threadIdx.x, lane = tid & 31, wid = tid >> 5;
    const int gr = lane >> 2, tc = lane & 3;
    const int wm = (wid < 7) ? wid : wid - 7;
    const int wn = (wid < 7) ? 0 : 1;
    const int colb = wm * 32;
    const int bid = blockIdx.x;

    int rs = (bid < 16) ? bid * 26 : 416 + (bid - 16) * 24;
    int re = rs + ((bid < 16) ? 26 : 24);

    // boundary halos (cols -1 and 224) are always zero: init once, all slots
    for (int idx = tid; idx < NSLOT * 64; idx += NTHR) {
        int slot = idx >> 6;
        int c = (idx & 63) >> 1, side = idx & 1;
        sx[slot * SLOTU + c * PXS + 3 + side * 225] = 0;
    }

    // weights -> smem once: 4608 chunks of 16B
    {
#pragma unroll
        for (int k = 0; k < 11; k++) {
            int chunk = tid + k * NTHR;
            if (chunk < 4608)
                cp16(wsa + (uint32_t)chunk * 16, (const char*)g_twB + (size_t)chunk * 16, 16);
        }
        asm volatile("cp.async.commit_group;" ::: "memory");
    }

    float als[4][2], bis[4][2];
#pragma unroll
    for (int nt = 0; nt < 4; nt++) {
        int co = wn * 32 + nt * 8 + 2 * tc;
        als[nt][0] = g_alpha[co];     als[nt][1] = g_alpha[co + 1];
        bis[nt][0] = bias[co];        bis[nt][1] = bias[co + 1];
    }

    while (rs < re) {
        const int n = rs / Hdim;
        const int h0 = rs - n * Hdim;
        const int hend = min(re - n * Hdim, Hdim);   // even length segment

        cp_stage(sxa, n, h0 - 1, tid);
        cp_stage(sxa, n, h0,     tid);
        cp_stage(sxa, n, h0 + 1, tid);
        cp_stage(sxa, n, h0 + 2, tid);
        asm volatile("cp.async.wait_group 0;" ::: "memory");
        __syncthreads();

        for (int h = h0; h < hend; h += 2) {
            float acc[2][2][4][4];     // [row r][mt][nt][e]
#pragma unroll
            for (int r = 0; r < 2; r++)
#pragma unroll
                for (int mt = 0; mt < 2; mt++)
#pragma unroll
                    for (int nt = 0; nt < 4; nt++)
#pragma unroll
                        for (int e = 0; e < 4; e++) acc[r][mt][nt][e] = 0.0f;

            // ---- phase 1: xr = 0 (input row h-1), contributes to row h with kh=0 ----
            {
                const uint32_t* slotp = sx + ((h - 1 + NSLOT * 2) % NSLOT) * SLOTU;
#pragma unroll
                for (int kw = 0; kw < 3; kw++) {
                    const uint32_t* ap_base = slotp + tc * PXS + 3 + colb + kw + gr;
                    const uint2* bq0 = B64 + (((kw * 4) * 8 + wn * 4) * 32 + gr * 4 + tc);
#pragma unroll
                    for (int ks = 0; ks < 4; ks++) {
                        uint32_t A[2][4];
                        LOAD_A(A, ap_base + (8 * ks) * PXS);
                        const uint2* bq = bq0 + ks * 256;
#pragma unroll
                        for (int nt = 0; nt < 4; nt++) {
                            uint2 b = bq[nt * 32];
                            mma_h(acc[0][0][nt], A[0], b.x, b.y);
                            mma_h(acc[0][1][nt], A[1], b.x, b.y);
                        }
                    }
                }
            }
            __syncthreads();     // all reads of slot(h-1) complete (prev iter + phase1)

            // stage rows h+3 -> slot(h-2), h+4 -> slot(h-1)
            cp_stage(sxa, n, h + 3, tid);
            cp_stage(sxa, n, h + 4, tid);
            asm volatile("cp.async.wait_group 2;" ::: "memory");   // rows h+1, h+2 landed
            __syncthreads();

            // ---- phase 2: xr = 1..3 (input rows h..h+2) ----
#pragma unroll
            for (int xr = 1; xr < 4; xr++) {
                const uint32_t* slotp = sx + ((h - 1 + xr + NSLOT * 2) % NSLOT) * SLOTU;
#pragma unroll
                for (int kw = 0; kw < 3; kw++) {
                    const uint32_t* ap_base = slotp + tc * PXS + 3 + colb + kw + gr;
#pragma unroll
                    for (int ks = 0; ks < 4; ks++) {
                        uint32_t A[2][4];
                        LOAD_A(A, ap_base + (8 * ks) * PXS);
                        if (xr < 3) {      // row h, kh = xr
                            const uint2* bq = B64 +
                                ((((xr * 3 + kw) * 4 + ks) * 8 + wn * 4) * 32 + gr * 4 + tc);
#pragma unroll
                            for (int nt = 0; nt < 4; nt++) {
                                uint2 b = bq[nt * 32];
                                mma_h(acc[0][0][nt], A[0], b.x, b.y);
                                mma_h(acc[0][1][nt], A[1], b.x, b.y);
                            }
                        }
                        {                  // row h+1, kh = xr-1
                            const uint2* bq = B64 +
                                (((((xr - 1) * 3 + kw) * 4 + ks) * 8 + wn * 4) * 32 + gr * 4 + tc);
#pragma unroll
                            for (int nt = 0; nt < 4; nt++) {
                                uint2 b = bq[nt * 32];
                                mma_h(acc[1][0][nt], A[0], b.x, b.y);
                                mma_h(acc[1][1][nt], A[1], b.x, b.y);
                            }
                        }
                    }
                }
            }

            // ---- epilogue: 2 rows ----
#pragma unroll
            for (int r = 0; r < 2; r++) {
                const int hr = h + r;
#pragma unroll
                for (int mt = 0; mt < 2; mt++) {
#pragma unroll
                    for (int nt = 0; nt < 4; nt++) {
                        int co = wn * 32 + nt * 8 + 2 * tc;
                        int wg = colb + mt * 16 + gr;
                        float* p = out + ((size_t)(n * C_OUT + co)) * HW + (size_t)hr * Wdim + wg;
                        p[0]      = acc[r][mt][nt][0] * als[nt][0] + bis[nt][0];
                        p[HW]     = acc[r][mt][nt][1] * als[nt][1] + bis[nt][1];
                        p[8]      = acc[r][mt][nt][2] * als[nt][0] + bis[nt][0];
                        p[HW + 8] = acc[r][mt][nt][3] * als[nt][1] + bis[nt][1];
                    }
                }
            }
            // ring safety across iterations:
            //  - next iter phase1 reads row h+1 (landed, visible since pre-phase2 bar)
            //  - next iter writes slots (h),(h+1) only after ITS phase1 bar.
        }

        asm volatile("cp.async.wait_group 0;" ::: "memory");   // drain before re-priming slots
        __syncthreads();
        rs = n * Hdim + hend;
    }
}

extern "C" void kernel_launch(void* const* d_in, const int* in_sizes, int n_in,
                              void* d_out, int out_size) {
    const float* x      = (const float*)d_in[0];
    const float* weight = (const float*)d_in[1];
    const float* bias   = (const float*)d_in[2];
    float* out          = (float*)d_out;

    cudaFuncSetAttribute(conv_kernel, cudaFuncAttributeMaxDynamicSharedMemorySize,
                         SMEM_TOTAL);

    prepass_kernel<<<16 * 32 * HW / 4 / 256, 256>>>(x);
    ternarize_kernel<<<C_OUT, 256>>>(weight);

    conv_kernel<<<148, NTHR, SMEM_TOTAL>>>(bias, out);
}

// round 15
// speedup vs baseline: 1.0004x; 1.0004x over previous
#include <cuda_runtime.h>
#include <cuda_fp16.h>
#include <cstdint>

#define C_IN   64
#define C_OUT  64
#define Hdim   224
#define Wdim   224
#define HW     (Hdim * Wdim)
#define NTHR   448

// B weight smem: u64 units, index = ((tap*4+ks)*8 + wn*4 + nt)*32 + gr*4 + tc
#define WS_BYTES (9 * 4 * 8 * 32 * 8)   // 73728
#define X_OFF    WS_BYTES
// fp16 x ring: 5 slots x [cipair 32 (stride 232 u32)]; halo j=3 (col -1), interior j=4..227, halo j=228
#define PXS    232
#define SLOTU  (32 * PXS)               // 7424 u32
#define NSLOT  5
#define SMEM_TOTAL (X_OFF + NSLOT * SLOTU * 4)   // 222208 B

// packed fp16 ci-pairs of x: [n][cipair 32][h][w]
__device__ __align__(16) uint32_t g_xh[16 * 32 * HW];
// ternary weights, LDS.64-friendly fragment layout (see ternarize)
__device__ __align__(16) unsigned short g_twB[9 * 4 * 8 * 32 * 4];
__device__ float g_alpha[C_OUT];

// ---------------------------------------------------------------- helpers
__device__ __forceinline__ uint32_t smem_u32(const void* p) {
    uint32_t a;
    asm("{ .reg .u64 t; cvta.to.shared.u64 t, %1; cvt.u32.u64 %0, t; }" : "=r"(a) : "l"(p));
    return a;
}
__device__ __forceinline__ void cp16(uint32_t dst, const void* src, int sz) {
    asm volatile("cp.async.cg.shared.global [%0], [%1], 16, %2;"
                 :: "r"(dst), "l"(src), "r"(sz) : "memory");
}
__device__ __forceinline__ uint32_t packh2(float lo, float hi) {
    return (uint32_t)__half_as_ushort(__float2half_rn(lo)) |
           ((uint32_t)__half_as_ushort(__float2half_rn(hi)) << 16);
}
__device__ __forceinline__ void mma_h(float* c, const uint32_t* a, uint32_t b0, uint32_t b1) {
    asm volatile(
        "mma.sync.aligned.m16n8k16.row.col.f32.f16.f16.f32 "
        "{%0,%1,%2,%3}, {%4,%5,%6,%7}, {%8,%9}, {%0,%1,%2,%3};"
        : "+f"(c[0]), "+f"(c[1]), "+f"(c[2]), "+f"(c[3])
        : "r"(a[0]), "r"(a[1]), "r"(a[2]), "r"(a[3]), "r"(b0), "r"(b1));
}

// ---------------------------------------------------------------- prepass: f32 -> packed fp16 pairs
__global__ void __launch_bounds__(256) prepass_kernel(const float* __restrict__ x) {
    int idx = blockIdx.x * 256 + threadIdx.x;
    int u = idx * 4;
    int n = u / (32 * HW);
    int r = u - n * (32 * HW);
    int c = r / HW;
    int p = r - c * HW;
    const float4 a = *(const float4*)(x + ((size_t)(n * 64 + 2 * c) * HW + p));
    const float4 b = *(const float4*)(x + ((size_t)(n * 64 + 2 * c + 1) * HW + p));
    uint4 o;
    o.x = packh2(a.x, b.x);
    o.y = packh2(a.y, b.y);
    o.z = packh2(a.z, b.z);
    o.w = packh2(a.w, b.w);
    *(uint4*)(g_xh + u) = o;
}

// ---------------------------------------------------------------- ternarize
__global__ void ternarize_kernel(const float* __restrict__ weight) {
    __shared__ float red[256], red2[256];
    __shared__ float s_delta, s_alpha;
    const int co = blockIdx.x, tid = threadIdx.x;
    const float* w = weight + co * 576;

    float v0 = (tid < 576) ? w[tid] : 0.0f;
    float v1 = (tid + 256 < 576) ? w[tid + 256] : 0.0f;
    float v2 = (tid + 512 < 576) ? w[tid + 512] : 0.0f;
    float a0 = fabsf(v0), a1 = fabsf(v1), a2 = fabsf(v2);

    red[tid] = a0 + a1 + a2;
    __syncthreads();
    for (int s = 128; s > 0; s >>= 1) { if (tid < s) red[tid] += red[tid + s]; __syncthreads(); }
    if (tid == 0) s_delta = (float)(0.7 / 576.0) * red[0];
    __syncthreads();
    const float delta = s_delta;

    float m0 = (a0 > delta) ? 1.f : 0.f, m1 = (a1 > delta) ? 1.f : 0.f, m2 = (a2 > delta) ? 1.f : 0.f;
    red[tid] = m0 * a0 + m1 * a1 + m2 * a2;
    red2[tid] = m0 + m1 + m2;
    __syncthreads();
    for (int s = 128; s > 0; s >>= 1) {
        if (tid < s) { red[tid] += red[tid + s]; red2[tid] += red2[tid + s]; }
        __syncthreads();
    }
    if (tid == 0) {
        float cnt = red2[0]; if (cnt < 0.5f) cnt = 1.0f;
        s_alpha = fmaxf(red[0] / cnt, 1e-4f);
        g_alpha[co] = s_alpha;
    }
    __syncthreads();

    const int wn = co >> 5, nt = (co >> 3) & 3, grb = co & 7;
#pragma unroll
    for (int q = 0; q < 3; q++) {
        int f = tid + q * 256;
        if (f < 576) {
            float v = (q == 0) ? v0 : (q == 1) ? v1 : v2;
            float t = (v > delta) ? 1.0f : ((v < -delta) ? -1.0f : 0.0f);
            int ci = f / 9, tap = f % 9;     // weight layout [co][ci][kh][kw]
            int ks = ci >> 4, r = ci & 15;
            int word = r >> 3, rr = r & 7;
            int tcb = rr >> 1, e = rr & 1;
            int u64idx = (((tap * 4 + ks) * 8 + wn * 4 + nt) * 32) + grb * 4 + tcb;
            g_twB[u64idx * 4 + word * 2 + e] = __half_as_ushort(__float2half_rn(t));
        }
    }
}

// ---------------------------------------------------------------- row staging (cp.async, one group per row)
// 32 cipairs x 56 chunks (224 cols / 4) = 1792 chunks = 4 per thread
__device__ __forceinline__ void cp_stage(uint32_t sxa, int n, int row, int tid) {
    const bool rok = (unsigned)row < (unsigned)Hdim;
    const int srow = rok ? row : 0;
    const int sz16 = rok ? 16 : 0;
    const uint32_t slot_b = sxa + (uint32_t)((row + NSLOT * 2) % NSLOT) * (SLOTU * 4);
    const uint32_t* xb = g_xh + (size_t)n * 32 * HW + (size_t)srow * Wdim;
#pragma unroll
    for (int k = 0; k < 4; k++) {
        int idx = tid + k * NTHR;            // 0..1791
        int c = idx / 56;                    // cipair 0..31
        int q = (idx - c * 56) * 4;          // col 0..220
        cp16(slot_b + (uint32_t)(c * PXS + 4 + q) * 4,
             xb + (size_t)c * HW + q, sz16);
    }
    asm volatile("cp.async.commit_group;" ::: "memory");
}

// A fragment load (one kstep, 2 m-tiles)
#define LOAD_A(A, ap)                                  \
    do {                                               \
        const uint32_t* _a0 = (ap);                    \
        (A)[0][0] = _a0[0];                            \
        (A)[0][1] = _a0[8];                            \
        (A)[0][2] = _a0[4 * PXS];                      \
        (A)[0][3] = _a0[4 * PXS + 8];                  \
        const uint32_t* _a1 = (ap) + 16;               \
        (A)[1][0] = _a1[0];                            \
        (A)[1][1] = _a1[8];                            \
        (A)[1][2] = _a1[4 * PXS];                      \
        (A)[1][3] = _a1[4 * PXS + 8];                  \
    } while (0)

// ---------------------------------------------------------------- conv (persistent, 2 rows/iter)
// grid (148). 448 thr = 14 warps: 7 M-warps (32 px, full 224 row) x 2 N-warps (32 co).
// Chunks: first 16 CTAs take 26 rows, remaining 132 take 24 (16*26 + 132*24 = 3584).
// All chunk starts even, image boundary (224) even -> every segment has even length.
__global__ void __launch_bounds__(NTHR, 1)
conv_kernel(const float* __restrict__ bias, float* __restrict__ out) {
    extern __shared__ char smem[];
    const uint2* B64 = (const uint2*)smem;
    uint32_t* sx = (uint32_t*)(smem + X_OFF);
    const uint32_t wsa = smem_u32(smem);
    const uint32_t sxa = smem_u32(smem + X_OFF);

    const int tid = threadIdx.x, lane = tid & 31, wid = tid >> 5;
    const int gr = lane >> 2, tc = lane & 3;
    const int wm = (wid < 7) ? wid : wid - 7;
    const int wn = (wid < 7) ? 0 : 1;
    const int colb = wm * 32;
    const int bid = blockIdx.x;

    int rs = (bid < 16) ? bid * 26 : 416 + (bid - 16) * 24;
    int re = rs + ((bid < 16) ? 26 : 24);

    // boundary halos (cols -1 and 224) are always zero: init once, all slots
    for (int idx = tid; idx < NSLOT * 64; idx += NTHR) {
        int slot = idx >> 6;
        int c = (idx & 63) >> 1, side = idx & 1;
        sx[slot * SLOTU + c * PXS + 3 + side * 225] = 0;
    }

    // weights -> smem once: 4608 chunks of 16B
    {
#pragma unroll
        for (int k = 0; k < 11; k++) {
            int chunk = tid + k * NTHR;
            if (chunk < 4608)
                cp16(wsa + (uint32_t)chunk * 16, (const char*)g_twB + (size_t)chunk * 16, 16);
        }
        asm volatile("cp.async.commit_group;" ::: "memory");
    }

    float als[4][2], bis[4][2];
#pragma unroll
    for (int nt = 0; nt < 4; nt++) {
        int co = wn * 32 + nt * 8 + 2 * tc;
        als[nt][0] = g_alpha[co];     als[nt][1] = g_alpha[co + 1];
        bis[nt][0] = bias[co];        bis[nt][1] = bias[co + 1];
    }

    while (rs < re) {
        const int n = rs / Hdim;
        const int h0 = rs - n * Hdim;
        const int hend = min(re - n * Hdim, Hdim);   // even length segment

        cp_stage(sxa, n, h0 - 1, tid);
        cp_stage(sxa, n, h0,     tid);
        cp_stage(sxa, n, h0 + 1, tid);
        cp_stage(sxa, n, h0 + 2, tid);
        asm volatile("cp.async.wait_group 0;" ::: "memory");
        __syncthreads();

        for (int h = h0; h < hend; h += 2) {
            float acc[2][2][4][4];     // [row r][mt][nt][e]
#pragma unroll
            for (int r = 0; r < 2; r++)
#pragma unroll
                for (int mt = 0; mt < 2; mt++)
#pragma unroll
                    for (int nt = 0; nt < 4; nt++)
#pragma unroll
                        for (int e = 0; e < 4; e++) acc[r][mt][nt][e] = 0.0f;

            // ---- phase 1: xr = 0 (input row h-1), contributes to row h with kh=0 ----
            {
                const uint32_t* slotp = sx + ((h - 1 + NSLOT * 2) % NSLOT) * SLOTU;
#pragma unroll
                for (int kw = 0; kw < 3; kw++) {
                    const uint32_t* ap_base = slotp + tc * PXS + 3 + colb + kw + gr;
                    const uint2* bq0 = B64 + (((kw * 4) * 8 + wn * 4) * 32 + gr * 4 + tc);
#pragma unroll
                    for (int ks = 0; ks < 4; ks++) {
                        uint32_t A[2][4];
                        LOAD_A(A, ap_base + (8 * ks) * PXS);
                        const uint2* bq = bq0 + ks * 256;
#pragma unroll
                        for (int nt = 0; nt < 4; nt++) {
                            uint2 b = bq[nt * 32];
                            mma_h(acc[0][0][nt], A[0], b.x, b.y);
                            mma_h(acc[0][1][nt], A[1], b.x, b.y);
                        }
                    }
                }
            }
            __syncthreads();     // all reads of slot(h-1) complete (prev iter + phase1)

            // stage rows h+3 -> slot(h-2), h+4 -> slot(h-1)
            cp_stage(sxa, n, h + 3, tid);
            cp_stage(sxa, n, h + 4, tid);
            asm volatile("cp.async.wait_group 2;" ::: "memory");   // rows h+1, h+2 landed
            __syncthreads();

            // ---- phase 2: xr = 1..3 (input rows h..h+2) ----
#pragma unroll
            for (int xr = 1; xr < 4; xr++) {
                const uint32_t* slotp = sx + ((h - 1 + xr + NSLOT * 2) % NSLOT) * SLOTU;
#pragma unroll
                for (int kw = 0; kw < 3; kw++) {
                    const uint32_t* ap_base = slotp + tc * PXS + 3 + colb + kw + gr;
#pragma unroll
                    for (int ks = 0; ks < 4; ks++) {
                        uint32_t A[2][4];
                        LOAD_A(A, ap_base + (8 * ks) * PXS);
                        if (xr < 3) {      // row h, kh = xr
                            const uint2* bq = B64 +
                                ((((xr * 3 + kw) * 4 + ks) * 8 + wn * 4) * 32 + gr * 4 + tc);
#pragma unroll
                            for (int nt = 0; nt < 4; nt++) {
                                uint2 b = bq[nt * 32];
                                mma_h(acc[0][0][nt], A[0], b.x, b.y);
                                mma_h(acc[0][1][nt], A[1], b.x, b.y);
                            }
                        }
                        {                  // row h+1, kh = xr-1
                            const uint2* bq = B64 +
                                (((((xr - 1) * 3 + kw) * 4 + ks) * 8 + wn * 4) * 32 + gr * 4 + tc);
#pragma unroll
                            for (int nt = 0; nt < 4; nt++) {
                                uint2 b = bq[nt * 32];
                                mma_h(acc[1][0][nt], A[0], b.x, b.y);
                                mma_h(acc[1][1][nt], A[1], b.x, b.y);
                            }
                        }
                    }
                }
            }

            // ---- epilogue: 2 rows ----
#pragma unroll
            for (int r = 0; r < 2; r++) {
                const int hr = h + r;
#pragma unroll
                for (int mt = 0; mt < 2; mt++) {
#pragma unroll
                    for (int nt = 0; nt < 4; nt++) {
                        int co = wn * 32 + nt * 8 + 2 * tc;
                        int wg = colb + mt * 16 + gr;
                        float* p = out + ((size_t)(n * C_OUT + co)) * HW + (size_t)hr * Wdim + wg;
                        p[0]      = acc[r][mt][nt][0] * als[nt][0] + bis[nt][0];
                        p[HW]     = acc[r][mt][nt][1] * als[nt][1] + bis[nt][1];
                        p[8]      = acc[r][mt][nt][2] * als[nt][0] + bis[nt][0];
                        p[HW + 8] = acc[r][mt][nt][3] * als[nt][1] + bis[nt][1];
                    }
                }
            }
            // ring safety across iterations:
            //  - next iter phase1 reads row h+1 (landed, visible since pre-phase2 bar)
            //  - next iter writes slots (h),(h+1) only after ITS phase1 bar.
        }

        asm volatile("cp.async.wait_group 0;" ::: "memory");   // drain before re-priming slots
        __syncthreads();
        rs = n * Hdim + hend;
    }
}

extern "C" void kernel_launch(void* const* d_in, const int* in_sizes, int n_in,
                              void* d_out, int out_size) {
    const float* x      = (const float*)d_in[0];
    const float* weight = (const float*)d_in[1];
    const float* bias   = (const float*)d_in[2];
    float* out          = (float*)d_out;

    cudaFuncSetAttribute(conv_kernel, cudaFuncAttributeMaxDynamicSharedMemorySize,
                         SMEM_TOTAL);

    prepass_kernel<<<16 * 32 * HW / 4 / 256, 256>>>(x);
    ternarize_kernel<<<C_OUT, 256>>>(weight);

    conv_kernel<<<148, NTHR, SMEM_TOTAL>>>(bias, out);
}

// round 16
// speedup vs baseline: 1.1106x; 1.1102x over previous
#include <cuda_runtime.h>
#include <cuda_fp16.h>
#include <cstdint>

#define C_IN   64
#define C_OUT  64
#define Hdim   224
#define Wdim   224
#define HW     (Hdim * Wdim)
#define NTHR   448

// B weight smem: u64 units, index = ((tap*4+ks)*8 + wn*4 + nt)*32 + gr*4 + tc
#define WS_BYTES (9 * 4 * 8 * 32 * 8)   // 73728
#define MB_OFF   WS_BYTES               // 5 mbarriers (8B each), pad to 64
#define X_OFF    (WS_BYTES + 64)
// fp16 x ring: 5 slots x [cipair 32 (stride 232 u32)]; halo j=3 (col -1), interior j=4..227, halo j=228
#define PXS    232
#define SLOTU  (32 * PXS)               // 7424 u32
#define NSLOT  5
#define ROW_BYTES (32 * 896)            // 28672 tx bytes per staged row
#define SMEM_TOTAL (X_OFF + NSLOT * SLOTU * 4)   // 222272 B

// packed fp16 ci-pairs of x: [n][cipair 32][h][w]
__device__ __align__(16) uint32_t g_xh[16 * 32 * HW];
// ternary weights, LDS.64-friendly fragment layout (see ternarize)
__device__ __align__(16) unsigned short g_twB[9 * 4 * 8 * 32 * 4];
__device__ float g_alpha[C_OUT];

// ---------------------------------------------------------------- helpers
__device__ __forceinline__ uint32_t smem_u32(const void* p) {
    uint32_t a;
    asm("{ .reg .u64 t; cvta.to.shared.u64 t, %1; cvt.u32.u64 %0, t; }" : "=r"(a) : "l"(p));
    return a;
}
__device__ __forceinline__ void cp16(uint32_t dst, const void* src, int sz) {
    asm volatile("cp.async.cg.shared.global [%0], [%1], 16, %2;"
                 :: "r"(dst), "l"(src), "r"(sz) : "memory");
}
__device__ __forceinline__ void bulk_g2s(uint32_t dst, const void* src, uint32_t bytes,
                                         uint32_t mb) {
    asm volatile(
        "cp.async.bulk.shared::cluster.global.mbarrier::complete_tx::bytes [%0], [%1], %2, [%3];"
        :: "r"(dst), "l"(src), "r"(bytes), "r"(mb) : "memory");
}
__device__ __forceinline__ void mbar_init(uint32_t mb, uint32_t cnt) {
    asm volatile("mbarrier.init.shared.b64 [%0], %1;" :: "r"(mb), "r"(cnt) : "memory");
}
__device__ __forceinline__ void mbar_expect_tx(uint32_t mb, uint32_t bytes) {
    asm volatile("mbarrier.arrive.expect_tx.shared.b64 _, [%0], %1;"
                 :: "r"(mb), "r"(bytes) : "memory");
}
__device__ __forceinline__ void mbar_arrive(uint32_t mb) {
    asm volatile("mbarrier.arrive.shared.b64 _, [%0];" :: "r"(mb) : "memory");
}
__device__ __forceinline__ void mbar_wait(uint32_t mb, uint32_t par) {
    uint32_t done;
    asm volatile(
        "{ .reg .pred p; mbarrier.try_wait.parity.acquire.cta.shared::cta.b64 p, [%1], %2;"
        " selp.b32 %0, 1, 0, p; }" : "=r"(done) : "r"(mb), "r"(par) : "memory");
    if (!done) {
        asm volatile(
            "{ .reg .pred P1; WL_%=:"
            " mbarrier.try_wait.parity.acquire.cta.shared::cta.b64 P1, [%0], %1, 0x989680;"
            " @P1 bra.uni WD_%=; bra.uni WL_%=; WD_%=: }"
            :: "r"(mb), "r"(par) : "memory");
    }
}
__device__ __forceinline__ uint32_t packh2(float lo, float hi) {
    return (uint32_t)__half_as_ushort(__float2half_rn(lo)) |
           ((uint32_t)__half_as_ushort(__float2half_rn(hi)) << 16);
}
__device__ __forceinline__ void mma_h(float* c, const uint32_t* a, uint32_t b0, uint32_t b1) {
    asm volatile(
        "mma.sync.aligned.m16n8k16.row.col.f32.f16.f16.f32 "
        "{%0,%1,%2,%3}, {%4,%5,%6,%7}, {%8,%9}, {%0,%1,%2,%3};"
        : "+f"(c[0]), "+f"(c[1]), "+f"(c[2]), "+f"(c[3])
        : "r"(a[0]), "r"(a[1]), "r"(a[2]), "r"(a[3]), "r"(b0), "r"(b1));
}

// ---------------------------------------------------------------- prepass: f32 -> packed fp16 pairs
__global__ void __launch_bounds__(256) prepass_kernel(const float* __restrict__ x) {
    int idx = blockIdx.x * 256 + threadIdx.x;
    int u = idx * 4;
    int n = u / (32 * HW);
    int r = u - n * (32 * HW);
    int c = r / HW;
    int p = r - c * HW;
    const float4 a = *(const float4*)(x + ((size_t)(n * 64 + 2 * c) * HW + p));
    const float4 b = *(const float4*)(x + ((size_t)(n * 64 + 2 * c + 1) * HW + p));
    uint4 o;
    o.x = packh2(a.x, b.x);
    o.y = packh2(a.y, b.y);
    o.z = packh2(a.z, b.z);
    o.w = packh2(a.w, b.w);
    *(uint4*)(g_xh + u) = o;
}

// ---------------------------------------------------------------- ternarize
__global__ void ternarize_kernel(const float* __restrict__ weight) {
    __shared__ float red[256], red2[256];
    __shared__ float s_delta, s_alpha;
    const int co = blockIdx.x, tid = threadIdx.x;
    const float* w = weight + co * 576;

    float v0 = (tid < 576) ? w[tid] : 0.0f;
    float v1 = (tid + 256 < 576) ? w[tid + 256] : 0.0f;
    float v2 = (tid + 512 < 576) ? w[tid + 512] : 0.0f;
    float a0 = fabsf(v0), a1 = fabsf(v1), a2 = fabsf(v2);

    red[tid] = a0 + a1 + a2;
    __syncthreads();
    for (int s = 128; s > 0; s >>= 1) { if (tid < s) red[tid] += red[tid + s]; __syncthreads(); }
    if (tid == 0) s_delta = (float)(0.7 / 576.0) * red[0];
    __syncthreads();
    const float delta = s_delta;

    float m0 = (a0 > delta) ? 1.f : 0.f, m1 = (a1 > delta) ? 1.f : 0.f, m2 = (a2 > delta) ? 1.f : 0.f;
    red[tid] = m0 * a0 + m1 * a1 + m2 * a2;
    red2[tid] = m0 + m1 + m2;
    __syncthreads();
    for (int s = 128; s > 0; s >>= 1) {
        if (tid < s) { red[tid] += red[tid + s]; red2[tid] += red2[tid + s]; }
        __syncthreads();
    }
    if (tid == 0) {
        float cnt = red2[0]; if (cnt < 0.5f) cnt = 1.0f;
        s_alpha = fmaxf(red[0] / cnt, 1e-4f);
        g_alpha[co] = s_alpha;
    }
    __syncthreads();

    const int wn = co >> 5, nt = (co >> 3) & 3, grb = co & 7;
#pragma unroll
    for (int q = 0; q < 3; q++) {
        int f = tid + q * 256;
        if (f < 576) {
            float v = (q == 0) ? v0 : (q == 1) ? v1 : v2;
            float t = (v > delta) ? 1.0f : ((v < -delta) ? -1.0f : 0.0f);
            int ci = f / 9, tap = f % 9;     // weight layout [co][ci][kh][kw]
            int ks = ci >> 4, r = ci & 15;
            int word = r >> 3, rr = r & 7;
            int tcb = rr >> 1, e = rr & 1;
            int u64idx = (((tap * 4 + ks) * 8 + wn * 4 + nt) * 32) + grb * 4 + tcb;
            g_twB[u64idx * 4 + word * 2 + e] = __half_as_ushort(__float2half_rn(t));
        }
    }
}

// ---------------------------------------------------------------- conv (persistent)
// grid (148). 448 thr = 14 warps: 7 M-warps (32 px, full 224 row) x 2 N-warps (32 co).
// Chunks: first 32 CTAs take 25 rows, remaining 116 take 24 (32*25 + 116*24 = 3584).
// Staging: warp 0 issues 32 cp.async.bulk (896B per cipair) per row; mbarrier/slot.
__global__ void __launch_bounds__(NTHR, 1)
conv_kernel(const float* __restrict__ bias, float* __restrict__ out) {
    extern __shared__ char smem[];
    const uint2* B64 = (const uint2*)smem;
    uint32_t* sx = (uint32_t*)(smem + X_OFF);
    const uint32_t wsa = smem_u32(smem);
    const uint32_t mba = smem_u32(smem + MB_OFF);
    const uint32_t sxa = smem_u32(smem + X_OFF);

    const int tid = threadIdx.x, lane = tid & 31, wid = tid >> 5;
    const int gr = lane >> 2, tc = lane & 3;
    const int wm = (wid < 7) ? wid : wid - 7;
    const int wn = (wid < 7) ? 0 : 1;
    const int colb = wm * 32;
    const int bid = blockIdx.x;

    int rs = (bid < 32) ? bid * 25 : 800 + (bid - 32) * 24;
    int re = rs + ((bid < 32) ? 25 : 24);

    // per-thread mbarrier phase tracking (identical across threads)
    int ph0 = 0, ph1 = 0, ph2 = 0, ph3 = 0, ph4 = 0;
    auto wait_slot = [&](int slot) {
        int p = (slot == 0) ? ph0 : (slot == 1) ? ph1 : (slot == 2) ? ph2
                                   : (slot == 3) ? ph3 : ph4;
        mbar_wait(mba + slot * 8, (uint32_t)p);
        if (slot == 0) ph0 ^= 1; else if (slot == 1) ph1 ^= 1;
        else if (slot == 2) ph2 ^= 1; else if (slot == 3) ph3 ^= 1; else ph4 ^= 1;
    };
    // staging: called by ALL threads
    auto stage_row = [&](int n, int row) {
        const int slot = (row + NSLOT * 2) % NSLOT;
        const uint32_t mb = mba + slot * 8;
        if ((unsigned)row < (unsigned)Hdim) {
            if (tid < 32) {
                if (tid == 0) mbar_expect_tx(mb, ROW_BYTES);
                __syncwarp();
                const char* src = (const char*)(g_xh + (size_t)n * 32 * HW
                                                + (size_t)tid * HW + (size_t)row * Wdim);
                uint32_t dst = sxa + (uint32_t)slot * (SLOTU * 4)
                             + (uint32_t)(tid * PXS + 4) * 4;
                bulk_g2s(dst, src, 896, mb);
            }
        } else {
            // zero fill (rows -1 / 224); visibility via the next __syncthreads chain
            uint32_t* sb = sx + slot * SLOTU;
#pragma unroll
            for (int k = 0; k < 4; k++) {
                int idx = tid + k * NTHR;
                int c = idx / 56;
                int q = (idx - c * 56) * 4;
                *(uint4*)(sb + c * PXS + 4 + q) = make_uint4(0, 0, 0, 0);
            }
            if (tid == 0) mbar_arrive(mb);
        }
    };

    // init: mbarriers + boundary halos (cols -1 and 224 always zero, all slots)
    if (tid < NSLOT) mbar_init(mba + tid * 8, 1);
    for (int idx = tid; idx < NSLOT * 64; idx += NTHR) {
        int slot = idx >> 6;
        int c = (idx & 63) >> 1, side = idx & 1;
        sx[slot * SLOTU + c * PXS + 3 + side * 225] = 0;
    }

    // weights -> smem once: 4608 chunks of 16B via cp.async
    {
#pragma unroll
        for (int k = 0; k < 11; k++) {
            int chunk = tid + k * NTHR;
            if (chunk < 4608)
                cp16(wsa + (uint32_t)chunk * 16, (const char*)g_twB + (size_t)chunk * 16, 16);
        }
        asm volatile("cp.async.commit_group;" ::: "memory");
        asm volatile("cp.async.wait_group 0;" ::: "memory");
    }
    __syncthreads();    // mbarriers initialized, weights + halos visible

    float als[4][2], bis[4][2];
#pragma unroll
    for (int nt = 0; nt < 4; nt++) {
        int co = wn * 32 + nt * 8 + 2 * tc;
        als[nt][0] = g_alpha[co];     als[nt][1] = g_alpha[co + 1];
        bis[nt][0] = bias[co];        bis[nt][1] = bias[co + 1];
    }

    while (rs < re) {
        const int n = rs / Hdim;
        const int h0 = rs - n * Hdim;
        const int hend = min(re - n * Hdim, Hdim);   // rows [h0, hend) of image n

        stage_row(n, h0 - 1);
        stage_row(n, h0);
        stage_row(n, h0 + 1);
        wait_slot((h0 - 1 + NSLOT * 2) % NSLOT);
        wait_slot((h0 + NSLOT * 2) % NSLOT);
        wait_slot((h0 + 1 + NSLOT * 2) % NSLOT);

        for (int h = h0; h < hend; h++) {
            if (h > h0) wait_slot((h + 1 + NSLOT * 2) % NSLOT);   // row h+1 landed
            __syncthreads();   // bounds WAR skew; publishes zero-fills / prior reads done
            if (h + 2 <= hend) stage_row(n, h + 2);

            float acc[2][4][4];
#pragma unroll
            for (int mt = 0; mt < 2; mt++)
#pragma unroll
                for (int nt = 0; nt < 4; nt++)
#pragma unroll
                    for (int e = 0; e < 4; e++) acc[mt][nt][e] = 0.0f;

#pragma unroll
            for (int kh = 0; kh < 3; kh++) {
                const uint32_t* slotp = sx + ((h + kh - 1 + NSLOT * 2) % NSLOT) * SLOTU;
#pragma unroll
                for (int kw = 0; kw < 3; kw++) {
                    const uint32_t* ap_base = slotp + tc * PXS + 3 + colb + kw + gr;
                    const uint2* bq0 = B64 + ((((kh * 3 + kw) * 4) * 8 + wn * 4) * 32 + gr * 4 + tc);
#pragma unroll
                    for (int ks = 0; ks < 4; ks++) {
                        const uint32_t* ap = ap_base + (8 * ks) * PXS;
                        const uint2* bq = bq0 + ks * 256;
                        uint32_t A[2][4];
#pragma unroll
                        for (int mt = 0; mt < 2; mt++) {
                            const uint32_t* a = ap + mt * 16;
                            A[mt][0] = a[0];
                            A[mt][1] = a[8];
                            A[mt][2] = a[4 * PXS];
                            A[mt][3] = a[4 * PXS + 8];
                        }
#pragma unroll
                        for (int nt = 0; nt < 4; nt++) {
                            uint2 b = bq[nt * 32];
                            mma_h(acc[0][nt], A[0], b.x, b.y);
                            mma_h(acc[1][nt], A[1], b.x, b.y);
                        }
                    }
                }
            }

            // epilogue
#pragma unroll
            for (int mt = 0; mt < 2; mt++) {
#pragma unroll
                for (int nt = 0; nt < 4; nt++) {
                    int co = wn * 32 + nt * 8 + 2 * tc;
                    int wg = colb + mt * 16 + gr;
                    float* p = out + ((size_t)(n * C_OUT + co)) * HW + (size_t)h * Wdim + wg;
                    p[0]      = acc[mt][nt][0] * als[nt][0] + bis[nt][0];
                    p[HW]     = acc[mt][nt][1] * als[nt][1] + bis[nt][1];
                    p[8]      = acc[mt][nt][2] * als[nt][0] + bis[nt][0];
                    p[HW + 8] = acc[mt][nt][3] * als[nt][1] + bis[nt][1];
                }
            }
        }
        __syncthreads();   // segment end: all reads done before next prime overwrites slots
        rs = n * Hdim + hend;
    }
}

extern "C" void kernel_launch(void* const* d_in, const int* in_sizes, int n_in,
                              void* d_out, int out_size) {
    const float* x      = (const float*)d_in[0];
    const float* weight = (const float*)d_in[1];
    const float* bias   = (const float*)d_in[2];
    float* out          = (float*)d_out;

    cudaFuncSetAttribute(conv_kernel, cudaFuncAttributeMaxDynamicSharedMemorySize,
                         SMEM_TOTAL);

    prepass_kernel<<<16 * 32 * HW / 4 / 256, 256>>>(x);
    ternarize_kernel<<<C_OUT, 256>>>(weight);

    conv_kernel<<<148, NTHR, SMEM_TOTAL>>>(bias, out);
}